// round 3
// baseline (speedup 1.0000x reference)
#include <cuda_runtime.h>
#include <cstdint>

#define BB 2
#define LL 2048
#define DD 1024
#define HH 16
#define DH 64
#define L3 3072

typedef unsigned long long ull;

// ---------------- f32x2 packed-math helpers (Blackwell) --------------------
__device__ __forceinline__ ull ffma2(ull a, ull b, ull c) {
    ull d;
    asm("fma.rn.f32x2 %0, %1, %2, %3;" : "=l"(d) : "l"(a), "l"(b), "l"(c));
    return d;
}
__device__ __forceinline__ ull fadd2(ull a, ull b) {
    ull d;
    asm("add.rn.f32x2 %0, %1, %2;" : "=l"(d) : "l"(a), "l"(b));
    return d;
}
__device__ __forceinline__ ull fdup(float x) {
    ull d;
    asm("mov.b64 %0, {%1, %1};" : "=l"(d) : "r"(__float_as_uint(x)));
    return d;
}
union U2 { ull u; float2 f; };

// ---------------- scratch (device globals; no allocations) ----------------
__device__ float g_qkv[(size_t)BB * LL * L3];        // [B*L, 3D]  50 MB
__device__ float g_ctx[(size_t)BB * LL * DD];        // context [B*L, D] 16 MB

// ---------- 128x128x8 SGEMM with f32x2: C = A(MxK) @ B(KxN) ----------------
__global__ __launch_bounds__(256) void sgemm_kernel(
    const float* __restrict__ A, const float* __restrict__ B,
    float* __restrict__ C, int M, int N, int K)
{
    __shared__ float As2[8][256];   // dup-stored A: As2[k][2i]=As2[k][2i+1]=A[i][k]
    __shared__ float Bs[8][128];
    const int t  = threadIdx.x;
    const int bm = blockIdx.y * 128;
    const int bn = blockIdx.x * 128;
    const int tx = t & 15, ty = t >> 4;

    ull acc[8][4];
#pragma unroll
    for (int i = 0; i < 8; i++)
#pragma unroll
        for (int j = 0; j < 4; j++) acc[i][j] = 0ull;

    const int arow = t >> 1, ako = (t & 1) * 4;
    const int brow = t >> 5, bno = (t & 31) * 4;

    for (int kt = 0; kt < K; kt += 8) {
        float4 av = *(const float4*)(A + (size_t)(bm + arow) * K + kt + ako);
        float4 bv = *(const float4*)(B + (size_t)(kt + brow) * N + bn + bno);
        *(float2*)&As2[ako + 0][2 * arow] = make_float2(av.x, av.x);
        *(float2*)&As2[ako + 1][2 * arow] = make_float2(av.y, av.y);
        *(float2*)&As2[ako + 2][2 * arow] = make_float2(av.z, av.z);
        *(float2*)&As2[ako + 3][2 * arow] = make_float2(av.w, av.w);
        *(float4*)&Bs[brow][bno] = bv;
        __syncthreads();
#pragma unroll
        for (int kk = 0; kk < 8; kk++) {
            const ulonglong2* ap = (const ulonglong2*)&As2[kk][ty * 16];
            ulonglong2 a01 = ap[0], a23 = ap[1], a45 = ap[2], a67 = ap[3];
            ull a[8] = {a01.x, a01.y, a23.x, a23.y, a45.x, a45.y, a67.x, a67.y};
            const ulonglong2* bp = (const ulonglong2*)&Bs[kk][tx * 8];
            ulonglong2 b01 = bp[0], b23 = bp[1];
            ull bb[4] = {b01.x, b01.y, b23.x, b23.y};
#pragma unroll
            for (int i = 0; i < 8; i++)
#pragma unroll
                for (int j = 0; j < 4; j++)
                    acc[i][j] = ffma2(a[i], bb[j], acc[i][j]);
        }
        __syncthreads();
    }
#pragma unroll
    for (int i = 0; i < 8; i++) {
        float* crow = C + (size_t)(bm + ty * 8 + i) * N + bn + tx * 8;
        ulonglong2 w0; w0.x = acc[i][0]; w0.y = acc[i][1];
        ulonglong2 w1; w1.x = acc[i][2]; w1.y = acc[i][3];
        *(ulonglong2*)(crow)     = w0;
        *(ulonglong2*)(crow + 4) = w1;
    }
}

// ------------- fused attention: QK^T + bias + softmax + align + PV ---------
// grid: (L/16, H, B), 256 threads.
// dyn smem: St[2048][18] (transposed S: St[k][r]) + region2:
//   QK phase : Qt[64][16] (Q transposed, scaled) + Ks[256][65]
//   PV phase : Vd[128][132] (V dup-stored: Vd[k][2d]=Vd[k][2d+1]=V[k][d])
#define ST_FLOATS   (2048 * 18)
#define R2_FLOATS   (1024 + 256 * 65)     // 17664 >= 128*132 = 16896
#define ATT_SMEM_BYTES ((ST_FLOATS + R2_FLOATS) * 4)

__global__ __launch_bounds__(256) void attn_fused_kernel(
    const float* __restrict__ qkv, const float* __restrict__ bias,
    float* __restrict__ ctx, float* __restrict__ align, int write_align)
{
    extern __shared__ float sm[];
    float* St = sm;                  // [2048][18]
    float* Qt = sm + ST_FLOATS;      // [64][16]
    float* Ks = Qt + 1024;           // [256][65]
    float* Vd = sm + ST_FLOATS;      // [128][132] (aliases Qt/Ks region)

    const int t  = threadIdx.x;
    const int q0 = blockIdx.x * 16;
    const int h  = blockIdx.y;
    const int b  = blockIdx.z;

    // ---- Phase A: load Q tile transposed + scaled (DH^-0.5 = 0.125) ----
    {
        int row = t >> 4, dd = (t & 15) * 4;
        float4 v = *(const float4*)(qkv + (size_t)(b * LL + q0 + row) * L3 + h * DH + dd);
        Qt[(dd + 0) * 16 + row] = v.x * 0.125f;
        Qt[(dd + 1) * 16 + row] = v.y * 0.125f;
        Qt[(dd + 2) * 16 + row] = v.z * 0.125f;
        Qt[(dd + 3) * 16 + row] = v.w * 0.125f;
    }

    // ---- Phase B: QK^T -> St[k][r] ----
    const int c0 = t & 127;
    const int rg = (t >> 7) * 8;     // rows rg..rg+7 (4 row-pairs)

    for (int jt = 0; jt < LL; jt += 256) {
        __syncthreads();
#pragma unroll
        for (int k = 0; k < 16; k++) {
            int i4  = t + k * 256;
            int row = i4 >> 4, dd = (i4 & 15) * 4;
            float4 v = *(const float4*)(qkv + (size_t)(b * LL + jt + row) * L3 + DD + h * DH + dd);
            float* kr = Ks + row * 65 + dd;
            kr[0] = v.x; kr[1] = v.y; kr[2] = v.z; kr[3] = v.w;
        }
        __syncthreads();

        ull acc[2][4];
#pragma unroll
        for (int p = 0; p < 4; p++) { acc[0][p] = 0ull; acc[1][p] = 0ull; }

        const float* K0 = Ks + c0 * 65;
        const float* K1 = Ks + (c0 + 128) * 65;
#pragma unroll 8
        for (int d = 0; d < DH; d++) {
            ulonglong2 q01 = *(const ulonglong2*)(Qt + d * 16 + rg);
            ulonglong2 q23 = *(const ulonglong2*)(Qt + d * 16 + rg + 4);
            ull k0d = fdup(K0[d]);
            ull k1d = fdup(K1[d]);
            acc[0][0] = ffma2(q01.x, k0d, acc[0][0]);
            acc[0][1] = ffma2(q01.y, k0d, acc[0][1]);
            acc[0][2] = ffma2(q23.x, k0d, acc[0][2]);
            acc[0][3] = ffma2(q23.y, k0d, acc[0][3]);
            acc[1][0] = ffma2(q01.x, k1d, acc[1][0]);
            acc[1][1] = ffma2(q01.y, k1d, acc[1][1]);
            acc[1][2] = ffma2(q23.x, k1d, acc[1][2]);
            acc[1][3] = ffma2(q23.y, k1d, acc[1][3]);
        }
#pragma unroll
        for (int p = 0; p < 4; p++) {
            *(ull*)&St[(jt + c0)       * 18 + rg + 2 * p] = acc[0][p];
            *(ull*)&St[(jt + c0 + 128) * 18 + rg + 2 * p] = acc[1][p];
        }
    }
    __syncthreads();

    // ---- Phase C: softmax over k for each of the 16 rows ----
    {
        const int warp = t >> 5, lane = t & 31;
        const float* brow = bias + (size_t)b * LL;
        for (int r = warp; r < 16; r += 8) {
            float m = -1e30f;
            for (int j = lane; j < LL; j += 32) {
                float v = St[j * 18 + r] + brow[j];
                St[j * 18 + r] = v;
                m = fmaxf(m, v);
            }
#pragma unroll
            for (int o = 16; o; o >>= 1) m = fmaxf(m, __shfl_xor_sync(0xffffffffu, m, o));
            float s = 0.f;
            for (int j = lane; j < LL; j += 32) {
                float e = __expf(St[j * 18 + r] - m);
                St[j * 18 + r] = e;
                s += e;
            }
#pragma unroll
            for (int o = 16; o; o >>= 1) s += __shfl_xor_sync(0xffffffffu, s, o);
            float inv = 1.0f / s;
            for (int j = lane; j < LL; j += 32) St[j * 18 + r] *= inv;
        }
    }
    __syncthreads();

    // ---- Phase D: align[b,h,j,q0..q0+16) — contiguous from St rows ----
    if (write_align) {
        float* ap = align + ((size_t)(b * HH + h) * LL) * LL + q0;
#pragma unroll
        for (int k = 0; k < 64; k++) {
            int i = t + k * 256;           // 2048 j * 8 float2-groups
            int j = i >> 3;
            int g = (i & 7) * 2;
            float2 v = *(const float2*)&St[j * 18 + g];
            *(float2*)(ap + (size_t)j * LL + g) = v;
        }
    }

    // ---- Phase E: PV  ctx[16][64] = St^T @ V ----
    {
        const int prg = t >> 6;          // 0..3 : rows 4*prg .. 4*prg+3
        const int cg  = (t >> 3) & 7;    // 0..7 : cols 8*cg .. 8*cg+7
        const int ks  = t & 7;           // k-split within warp

        ull acc[2][8];
#pragma unroll
        for (int p = 0; p < 2; p++)
#pragma unroll
            for (int j = 0; j < 8; j++) acc[p][j] = 0ull;

        for (int kt = 0; kt < LL; kt += 128) {
            __syncthreads();
#pragma unroll
            for (int k2 = 0; k2 < 8; k2++) {
                int i4  = t + k2 * 256;
                int row = i4 >> 4, dd = (i4 & 15) * 4;
                float4 v = *(const float4*)(qkv + (size_t)(b * LL + kt + row) * L3 + 2 * DD + h * DH + dd);
                float* vr = Vd + row * 132 + 2 * dd;
                *(float2*)(vr + 0) = make_float2(v.x, v.x);
                *(float2*)(vr + 2) = make_float2(v.y, v.y);
                *(float2*)(vr + 4) = make_float2(v.z, v.z);
                *(float2*)(vr + 6) = make_float2(v.w, v.w);
            }
            __syncthreads();

#pragma unroll 4
            for (int kk = ks; kk < 128; kk += 8) {
                // St row stride is 18 floats (72B) -> 16B vector loads would be
                // misaligned on odd rows; use two 8B loads (always 8B-aligned).
                ull sx = *(const ull*)&St[(kt + kk) * 18 + 4 * prg];
                ull sy = *(const ull*)&St[(kt + kk) * 18 + 4 * prg + 2];
                const ulonglong2* vp = (const ulonglong2*)&Vd[kk * 132 + 16 * cg];
                ulonglong2 v01 = vp[0], v23 = vp[1], v45 = vp[2], v67 = vp[3];
                ull vd[8] = {v01.x, v01.y, v23.x, v23.y, v45.x, v45.y, v67.x, v67.y};
#pragma unroll
                for (int j = 0; j < 8; j++) {
                    acc[0][j] = ffma2(sx, vd[j], acc[0][j]);
                    acc[1][j] = ffma2(sy, vd[j], acc[1][j]);
                }
            }
        }

        // reduce k-split partials across lanes (ks = lane&7)
#pragma unroll
        for (int p = 0; p < 2; p++)
#pragma unroll
            for (int j = 0; j < 8; j++) {
                ull a = acc[p][j];
                a = fadd2(a, __shfl_xor_sync(0xffffffffu, a, 1));
                a = fadd2(a, __shfl_xor_sync(0xffffffffu, a, 2));
                a = fadd2(a, __shfl_xor_sync(0xffffffffu, a, 4));
                acc[p][j] = a;
            }

        if (ks == 0) {
#pragma unroll
            for (int p = 0; p < 2; p++) {
#pragma unroll
                for (int j = 0; j < 8; j++) {
                    U2 u; u.u = acc[p][j];
                    int r0 = 4 * prg + 2 * p;
                    size_t base = ((size_t)(b * LL) + q0 + r0) * DD + h * DH + 8 * cg + j;
                    ctx[base]      = u.f.x;
                    ctx[base + DD] = u.f.y;
                }
            }
        }
    }
}

// --------------------------------- launch ----------------------------------
extern "C" void kernel_launch(void* const* d_in, const int* in_sizes, int n_in,
                              void* d_out, int out_size)
{
    const float* queries = (const float*)d_in[0];
    const float* bias    = (const float*)d_in[1];
    const float* w_qkv   = (const float*)d_in[2];
    const float* w_o     = (const float*)d_in[3];
    float* out = (float*)d_out;

    const size_t out_elems   = (size_t)BB * LL * DD;        // 4,194,304
    const size_t align_elems = (size_t)BB * HH * LL * LL;   // 134,217,728
    int write_align = ((size_t)out_size >= out_elems + align_elems) ? 1 : 0;
    float* align = out + out_elems;

    float *qkv_p = nullptr, *ctx_p = nullptr;
    cudaGetSymbolAddress((void**)&qkv_p, g_qkv);
    cudaGetSymbolAddress((void**)&ctx_p, g_ctx);

    cudaFuncSetAttribute(attn_fused_kernel,
                         cudaFuncAttributeMaxDynamicSharedMemorySize, ATT_SMEM_BYTES);

    // 1) QKV projection: [4096,1024] @ [1024,3072]
    {
        dim3 grid(L3 / 128, (BB * LL) / 128);
        sgemm_kernel<<<grid, 256>>>(queries, w_qkv, qkv_p, BB * LL, L3, DD);
    }
    // 2) fused attention: QK^T + bias + softmax + align + PV
    {
        dim3 grid(LL / 16, HH, BB);
        attn_fused_kernel<<<grid, 256, ATT_SMEM_BYTES>>>(qkv_p, bias, ctx_p, align, write_align);
    }
    // 3) output projection: [4096,1024] @ [1024,1024]
    {
        dim3 grid(DD / 128, (BB * LL) / 128);
        sgemm_kernel<<<grid, 256>>>(ctx_p, w_o, out, BB * LL, DD, DD);
    }
}

// round 4
// speedup vs baseline: 1.4145x; 1.4145x over previous
#include <cuda_runtime.h>
#include <cstdint>

#define BB 2
#define LL 2048
#define DD 1024
#define HH 16
#define DH 64
#define L3 3072

// ---------------- tf32 split + mma helpers ---------------------------------
__device__ __forceinline__ void split_tf32(float x, uint32_t& hi, uint32_t& lo) {
    asm("cvt.rna.tf32.f32 %0, %1;" : "=r"(hi) : "f"(x));
    float r = x - __uint_as_float(hi);
    asm("cvt.rna.tf32.f32 %0, %1;" : "=r"(lo) : "f"(r));
}
__device__ __forceinline__ void split_tf32_f(float x, float& hi, float& lo) {
    uint32_t h, l;
    asm("cvt.rna.tf32.f32 %0, %1;" : "=r"(h) : "f"(x));
    float hf = __uint_as_float(h);
    float r = x - hf;
    asm("cvt.rna.tf32.f32 %0, %1;" : "=r"(l) : "f"(r));
    hi = hf; lo = __uint_as_float(l);
}
__device__ __forceinline__ void mma8(float* c, const uint32_t* a, uint32_t b0, uint32_t b1) {
    asm volatile(
        "mma.sync.aligned.m16n8k8.row.col.f32.tf32.tf32.f32 "
        "{%0,%1,%2,%3}, {%4,%5,%6,%7}, {%8,%9}, {%0,%1,%2,%3};"
        : "+f"(c[0]), "+f"(c[1]), "+f"(c[2]), "+f"(c[3])
        : "r"(a[0]), "r"(a[1]), "r"(a[2]), "r"(a[3]), "r"(b0), "r"(b1));
}
__device__ __forceinline__ uint32_t fu(float x) { return __float_as_uint(x); }

// ---------------- scratch (device globals; no allocations) ----------------
__device__ float g_qkv[(size_t)BB * LL * L3];        // [B*L, 3D]  50 MB
__device__ float g_ctx[(size_t)BB * LL * DD];        // context [B*L, D] 16 MB

// ---------- split-TF32 GEMM: C = A(MxK) @ B(KxN), 128x128x32 tile ----------
#define GA_STRIDE 36
#define GB_STRIDE 132
#define SG_SMEM_FLOATS (2 * 128 * GA_STRIDE + 2 * 32 * GB_STRIDE)
#define SG_SMEM_BYTES  (SG_SMEM_FLOATS * 4)

__global__ __launch_bounds__(256) void sgemm_tf32(
    const float* __restrict__ A, const float* __restrict__ B,
    float* __restrict__ C, int M, int N, int K)
{
    extern __shared__ float smg[];
    float* Ahi = smg;                          // [128][36]
    float* Alo = Ahi + 128 * GA_STRIDE;
    float* Bhi = Alo + 128 * GA_STRIDE;        // [32][132]
    float* Blo = Bhi + 32 * GB_STRIDE;

    const int t = threadIdx.x;
    const int w = t >> 5, lane = t & 31;
    const int g = lane >> 2, tg = lane & 3;
    const int wm = w >> 2, wn = w & 3;
    const int bm = blockIdx.y * 128, bn = blockIdx.x * 128;

    float acc[4][4][4];
#pragma unroll
    for (int mi = 0; mi < 4; mi++)
#pragma unroll
        for (int ni = 0; ni < 4; ni++)
#pragma unroll
            for (int e = 0; e < 4; e++) acc[mi][ni][e] = 0.f;

    const int la_row = t >> 3, la_col = (t & 7) * 4;
    const int lb_row = t >> 5, lb_col = (t & 31) * 4;

    float4 pa[4], pb[4];
#pragma unroll
    for (int i = 0; i < 4; i++) {
        pa[i] = *(const float4*)(A + (size_t)(bm + la_row + 32 * i) * K + la_col);
        pb[i] = *(const float4*)(B + (size_t)(lb_row + 8 * i) * N + bn + lb_col);
    }

    for (int kt = 0; kt < K; kt += 32) {
        // split + store tiles
#pragma unroll
        for (int i = 0; i < 4; i++) {
            int row = la_row + 32 * i;
            float4 h4, l4;
            split_tf32_f(pa[i].x, h4.x, l4.x);
            split_tf32_f(pa[i].y, h4.y, l4.y);
            split_tf32_f(pa[i].z, h4.z, l4.z);
            split_tf32_f(pa[i].w, h4.w, l4.w);
            *(float4*)&Ahi[row * GA_STRIDE + la_col] = h4;
            *(float4*)&Alo[row * GA_STRIDE + la_col] = l4;
        }
#pragma unroll
        for (int i = 0; i < 4; i++) {
            int row = lb_row + 8 * i;
            float4 h4, l4;
            split_tf32_f(pb[i].x, h4.x, l4.x);
            split_tf32_f(pb[i].y, h4.y, l4.y);
            split_tf32_f(pb[i].z, h4.z, l4.z);
            split_tf32_f(pb[i].w, h4.w, l4.w);
            *(float4*)&Bhi[row * GB_STRIDE + lb_col] = h4;
            *(float4*)&Blo[row * GB_STRIDE + lb_col] = l4;
        }
        __syncthreads();

        if (kt + 32 < K) {
#pragma unroll
            for (int i = 0; i < 4; i++) {
                pa[i] = *(const float4*)(A + (size_t)(bm + la_row + 32 * i) * K + kt + 32 + la_col);
                pb[i] = *(const float4*)(B + (size_t)(kt + 32 + lb_row + 8 * i) * N + bn + lb_col);
            }
        }

#pragma unroll
        for (int ks = 0; ks < 4; ks++) {
            const int k0 = ks * 8;
            uint32_t ah[4][4], al[4][4];
#pragma unroll
            for (int mi = 0; mi < 4; mi++) {
                int rm = wm * 64 + mi * 16;
                ah[mi][0] = fu(Ahi[(rm + g)     * GA_STRIDE + k0 + tg]);
                ah[mi][1] = fu(Ahi[(rm + g + 8) * GA_STRIDE + k0 + tg]);
                ah[mi][2] = fu(Ahi[(rm + g)     * GA_STRIDE + k0 + tg + 4]);
                ah[mi][3] = fu(Ahi[(rm + g + 8) * GA_STRIDE + k0 + tg + 4]);
                al[mi][0] = fu(Alo[(rm + g)     * GA_STRIDE + k0 + tg]);
                al[mi][1] = fu(Alo[(rm + g + 8) * GA_STRIDE + k0 + tg]);
                al[mi][2] = fu(Alo[(rm + g)     * GA_STRIDE + k0 + tg + 4]);
                al[mi][3] = fu(Alo[(rm + g + 8) * GA_STRIDE + k0 + tg + 4]);
            }
#pragma unroll
            for (int ni = 0; ni < 4; ni++) {
                int nb = wn * 32 + ni * 8;
                uint32_t bh0 = fu(Bhi[(k0 + tg)     * GB_STRIDE + nb + g]);
                uint32_t bh1 = fu(Bhi[(k0 + tg + 4) * GB_STRIDE + nb + g]);
                uint32_t bl0 = fu(Blo[(k0 + tg)     * GB_STRIDE + nb + g]);
                uint32_t bl1 = fu(Blo[(k0 + tg + 4) * GB_STRIDE + nb + g]);
#pragma unroll
                for (int mi = 0; mi < 4; mi++) {
                    mma8(acc[mi][ni], ah[mi], bh0, bh1);
                    mma8(acc[mi][ni], ah[mi], bl0, bl1);
                    mma8(acc[mi][ni], al[mi], bh0, bh1);
                }
            }
        }
        __syncthreads();
    }

#pragma unroll
    for (int mi = 0; mi < 4; mi++) {
#pragma unroll
        for (int ni = 0; ni < 4; ni++) {
            int r0 = bm + wm * 64 + mi * 16 + g;
            int c0 = bn + wn * 32 + ni * 8 + 2 * tg;
            *(float2*)(C + (size_t)r0 * N + c0)       = make_float2(acc[mi][ni][0], acc[mi][ni][1]);
            *(float2*)(C + (size_t)(r0 + 8) * N + c0) = make_float2(acc[mi][ni][2], acc[mi][ni][3]);
        }
    }
}

// ------------- fused attention: QK^T + softmax + align + PV (MMA) ----------
// grid: (L/16, H, B), 256 threads.
// smem: St[2048][18] + Qs[16][72] + KVs[128][72]
#define ST_STRIDE 18
#define Q_STRIDE  72
#define KV_STRIDE 72
#define ATT_SMEM_FLOATS (2048 * ST_STRIDE + 16 * Q_STRIDE + 128 * KV_STRIDE)
#define ATT_SMEM_BYTES  (ATT_SMEM_FLOATS * 4)

__global__ __launch_bounds__(256) void attn_fused_kernel(
    const float* __restrict__ qkv, const float* __restrict__ bias,
    float* __restrict__ ctx, float* __restrict__ align, int write_align)
{
    extern __shared__ float sm[];
    float* St  = sm;                             // [2048][18]
    float* Qs  = sm + 2048 * ST_STRIDE;          // [16][72]
    float* KVs = Qs + 16 * Q_STRIDE;             // [128][72]

    const int t = threadIdx.x;
    const int w = t >> 5, lane = t & 31;
    const int g = lane >> 2, tg = lane & 3;
    const int q0 = blockIdx.x * 16;
    const int h  = blockIdx.y;
    const int b  = blockIdx.z;

    const float* kbase = qkv + (size_t)b * LL * L3 + DD + h * DH;
    const float* vbase = qkv + (size_t)b * LL * L3 + 2 * DD + h * DH;

    // ---- Phase A: Q tile, scaled by DH^-0.5 = 0.125 ----
    {
        int row = t >> 4, d4 = (t & 15) * 4;
        float4 v = *(const float4*)(qkv + (size_t)(b * LL + q0 + row) * L3 + h * DH + d4);
        v.x *= 0.125f; v.y *= 0.125f; v.z *= 0.125f; v.w *= 0.125f;
        *(float4*)&Qs[row * Q_STRIDE + d4] = v;
    }

    const int lrow = t >> 4;           // 0..15 (+16*i)
    const int ld4  = (t & 15) * 4;

    // ---- Phase B: QK^T via split-tf32 MMA, chunks of 128 keys ----
    float4 pk[8];
#pragma unroll
    for (int i = 0; i < 8; i++)
        pk[i] = *(const float4*)(kbase + (size_t)(lrow + 16 * i) * L3 + ld4);

    for (int jt = 0; jt < LL; jt += 128) {
        __syncthreads();
#pragma unroll
        for (int i = 0; i < 8; i++)
            *(float4*)&KVs[(lrow + 16 * i) * KV_STRIDE + ld4] = pk[i];
        __syncthreads();
        if (jt + 128 < LL) {
#pragma unroll
            for (int i = 0; i < 8; i++)
                pk[i] = *(const float4*)(kbase + (size_t)(jt + 128 + lrow + 16 * i) * L3 + ld4);
        }

        float acc2[2][4];
#pragma unroll
        for (int ni = 0; ni < 2; ni++)
#pragma unroll
            for (int e = 0; e < 4; e++) acc2[ni][e] = 0.f;

#pragma unroll
        for (int ks = 0; ks < 8; ks++) {
            const int k0 = ks * 8;
            uint32_t ah[4], al[4];
            split_tf32(Qs[g * Q_STRIDE + k0 + tg],           ah[0], al[0]);
            split_tf32(Qs[(g + 8) * Q_STRIDE + k0 + tg],     ah[1], al[1]);
            split_tf32(Qs[g * Q_STRIDE + k0 + tg + 4],       ah[2], al[2]);
            split_tf32(Qs[(g + 8) * Q_STRIDE + k0 + tg + 4], ah[3], al[3]);
#pragma unroll
            for (int ni = 0; ni < 2; ni++) {
                int nb = w * 16 + ni * 8;
                uint32_t bh0, bl0, bh1, bl1;
                split_tf32(KVs[(nb + g) * KV_STRIDE + k0 + tg],     bh0, bl0);
                split_tf32(KVs[(nb + g) * KV_STRIDE + k0 + tg + 4], bh1, bl1);
                mma8(acc2[ni], ah, bh0, bh1);
                mma8(acc2[ni], ah, bl0, bl1);
                mma8(acc2[ni], al, bh0, bh1);
            }
        }
#pragma unroll
        for (int ni = 0; ni < 2; ni++) {
            int j = jt + w * 16 + ni * 8 + 2 * tg;
            St[j * ST_STRIDE + g]           = acc2[ni][0];
            St[(j + 1) * ST_STRIDE + g]     = acc2[ni][1];
            St[j * ST_STRIDE + g + 8]       = acc2[ni][2];
            St[(j + 1) * ST_STRIDE + g + 8] = acc2[ni][3];
        }
    }
    __syncthreads();

    // prefetch first V chunk (overlaps softmax)
    float4 pv[8];
#pragma unroll
    for (int i = 0; i < 8; i++)
        pv[i] = *(const float4*)(vbase + (size_t)(lrow + 16 * i) * L3 + ld4);

    // ---- Phase C: softmax over keys for each of the 16 rows ----
    {
        const float* brow = bias + (size_t)b * LL;
        for (int r = w; r < 16; r += 8) {
            float m = -1e30f;
            for (int j = lane; j < LL; j += 32) {
                float v = St[j * ST_STRIDE + r] + brow[j];
                St[j * ST_STRIDE + r] = v;
                m = fmaxf(m, v);
            }
#pragma unroll
            for (int o = 16; o; o >>= 1) m = fmaxf(m, __shfl_xor_sync(0xffffffffu, m, o));
            float s = 0.f;
            for (int j = lane; j < LL; j += 32) {
                float e = __expf(St[j * ST_STRIDE + r] - m);
                St[j * ST_STRIDE + r] = e;
                s += e;
            }
#pragma unroll
            for (int o = 16; o; o >>= 1) s += __shfl_xor_sync(0xffffffffu, s, o);
            float inv = 1.0f / s;
            for (int j = lane; j < LL; j += 32) St[j * ST_STRIDE + r] *= inv;
        }
    }
    __syncthreads();

    // ---- Phase D: align[b,h,j,q0..q0+16) — contiguous float2 ----
    if (write_align) {
        float* ap = align + ((size_t)(b * HH + h) * LL) * LL + q0;
#pragma unroll
        for (int k = 0; k < 64; k++) {
            int i = t + k * 256;
            int j = i >> 3;
            int g2 = (i & 7) * 2;
            float2 v = *(const float2*)&St[j * ST_STRIDE + g2];
            *(float2*)(ap + (size_t)j * LL + g2) = v;
        }
    }

    // ---- Phase E: PV via split-tf32 MMA ----
    {
        const int n0 = w * 8;      // warp's 8 output dims
        float acc[4] = {0.f, 0.f, 0.f, 0.f};

        for (int kt = 0; kt < LL; kt += 128) {
            __syncthreads();
#pragma unroll
            for (int i = 0; i < 8; i++)
                *(float4*)&KVs[(lrow + 16 * i) * KV_STRIDE + ld4] = pv[i];
            __syncthreads();
            if (kt + 128 < LL) {
#pragma unroll
                for (int i = 0; i < 8; i++)
                    pv[i] = *(const float4*)(vbase + (size_t)(kt + 128 + lrow + 16 * i) * L3 + ld4);
            }

#pragma unroll
            for (int kk = 0; kk < 16; kk++) {
                const int kb = kt + kk * 8;
                const int lk = kk * 8;
                uint32_t ah[4], al[4];
                split_tf32(St[(kb + tg) * ST_STRIDE + g],         ah[0], al[0]);
                split_tf32(St[(kb + tg) * ST_STRIDE + g + 8],     ah[1], al[1]);
                split_tf32(St[(kb + tg + 4) * ST_STRIDE + g],     ah[2], al[2]);
                split_tf32(St[(kb + tg + 4) * ST_STRIDE + g + 8], ah[3], al[3]);
                uint32_t bh0, bl0, bh1, bl1;
                split_tf32(KVs[(lk + tg) * KV_STRIDE + n0 + g],     bh0, bl0);
                split_tf32(KVs[(lk + tg + 4) * KV_STRIDE + n0 + g], bh1, bl1);
                mma8(acc, ah, bh0, bh1);
                mma8(acc, ah, bl0, bl1);
                mma8(acc, al, bh0, bh1);
            }
        }

        float* cp = ctx + ((size_t)(b * LL) + q0) * DD + h * DH;
        *(float2*)(cp + (size_t)g * DD + n0 + 2 * tg)       = make_float2(acc[0], acc[1]);
        *(float2*)(cp + (size_t)(g + 8) * DD + n0 + 2 * tg) = make_float2(acc[2], acc[3]);
    }
}

// --------------------------------- launch ----------------------------------
extern "C" void kernel_launch(void* const* d_in, const int* in_sizes, int n_in,
                              void* d_out, int out_size)
{
    const float* queries = (const float*)d_in[0];
    const float* bias    = (const float*)d_in[1];
    const float* w_qkv   = (const float*)d_in[2];
    const float* w_o     = (const float*)d_in[3];
    float* out = (float*)d_out;

    const size_t out_elems   = (size_t)BB * LL * DD;
    const size_t align_elems = (size_t)BB * HH * LL * LL;
    int write_align = ((size_t)out_size >= out_elems + align_elems) ? 1 : 0;
    float* align = out + out_elems;

    float *qkv_p = nullptr, *ctx_p = nullptr;
    cudaGetSymbolAddress((void**)&qkv_p, g_qkv);
    cudaGetSymbolAddress((void**)&ctx_p, g_ctx);

    cudaFuncSetAttribute(sgemm_tf32,
                         cudaFuncAttributeMaxDynamicSharedMemorySize, SG_SMEM_BYTES);
    cudaFuncSetAttribute(attn_fused_kernel,
                         cudaFuncAttributeMaxDynamicSharedMemorySize, ATT_SMEM_BYTES);

    // 1) QKV projection: [4096,1024] @ [1024,3072]
    {
        dim3 grid(L3 / 128, (BB * LL) / 128);
        sgemm_tf32<<<grid, 256, SG_SMEM_BYTES>>>(queries, w_qkv, qkv_p, BB * LL, L3, DD);
    }
    // 2) fused attention: QK^T + bias + softmax + align + PV
    {
        dim3 grid(LL / 16, HH, BB);
        attn_fused_kernel<<<grid, 256, ATT_SMEM_BYTES>>>(qkv_p, bias, ctx_p, align, write_align);
    }
    // 3) output projection: [4096,1024] @ [1024,1024]
    {
        dim3 grid(DD / 128, (BB * LL) / 128);
        sgemm_tf32<<<grid, 256, SG_SMEM_BYTES>>>(ctx_p, w_o, out, BB * LL, DD, DD);
    }
}